// round 13
// baseline (speedup 1.0000x reference)
#include <cuda_runtime.h>
#include <cuda_bf16.h>

#define BMAX 16384

typedef unsigned long long u64;

// Scratch (static device globals — no allocation).
// Pair-interleaved layout: g_U4[p][o2][bh] (p<8, o2<10, bh<B/2), float4 =
//   { U[2bh][p][2o2], U[2bh][p][2o2+1], U[2bh+1][p][2o2], U[2bh+1][p][2o2+1] }
// (b_feat folded into U). Same for V. 10.5 MB each -> L2-resident.
__device__ float4 g_U4[8 * 10 * (BMAX / 2)];
__device__ float4 g_V4[8 * 10 * (BMAX / 2)];
// per-position relu(final) values, summed in groups of 7 by k3
__device__ float g_S[BMAX * 56];

// PHASE_LANES = [[1,3],[5,7],[0,2],[4,6],[0,1],[2,3],[4,5],[6,7]]
__device__ const int d_PLa[8] = {1, 5, 0, 4, 0, 2, 4, 6};
__device__ const int d_PLb[8] = {3, 7, 2, 6, 1, 3, 5, 7};

__device__ __forceinline__ float sigmoidf(float x) {
    return __fdividef(1.0f, 1.0f + __expf(-x));
}
__device__ __forceinline__ u64 pk2(float lo, float hi) {
    u64 r;
    asm("mov.b64 %0, {%1, %2};" : "=l"(r) : "f"(lo), "f"(hi));
    return r;
}
__device__ __forceinline__ void upk2(float& lo, float& hi, u64 v) {
    asm("mov.b64 {%0, %1}, %2;" : "=f"(lo), "=f"(hi) : "l"(v));
}
__device__ __forceinline__ u64 f2fma(u64 a, u64 b, u64 c) {
    u64 d;
    asm("fma.rn.f32x2 %0, %1, %2, %3;" : "=l"(d) : "l"(a), "l"(b), "l"(c));
    return d;
}
__device__ __forceinline__ u64 f2mul(u64 a, u64 b) {
    u64 d;
    asm("mul.rn.f32x2 %0, %1, %2;" : "=l"(d) : "l"(a), "l"(b));
    return d;
}

// ---------------------------------------------------------------------------
// Kernel 1: grid (B/256, 8); p = blockIdx.y, b fast across lanes.
// Inputs staged through smem (coalesced); lane MLP packed f32x2 over the
// (laneA, laneB) pair; projection packed f32x2 over (U,V) with LDS.128
// weight reads; sigmoid(emb_phase) precomputed per block.
// ---------------------------------------------------------------------------
__global__ void __launch_bounds__(256, 2)
frap_k1(const float* __restrict__ fi,
        const float* __restrict__ emb_phase,
        const float* __restrict__ w_veh,
        const float* __restrict__ b_veh,
        const float* __restrict__ w_line,
        const float* __restrict__ b_line,
        const float* __restrict__ w_feat,
        const float* __restrict__ b_feat,
        int B)
{
    __shared__ __align__(16) float s_fi[256 * 17];        // padded input tile
    __shared__ __align__(16) u64   s_wline2[128];         // dup-packed (16,8)
    __shared__ __align__(16) ulonglong2 s_wpk2[160];      // [o2][c]: (wA_pk, wB_pk)
    __shared__ u64   s_bline2[16];
    __shared__ float s_bfeat[20];
    __shared__ float s_sge[8];                            // sigmoid(emb_phase)
    __shared__ float s_wv[4], s_bv[4];

    int tx = threadIdx.x;
    int base = blockIdx.x * 256;

    // coalesced staging of the input tile (256 rows x 16 floats)
    {
        const float4* fi4 = (const float4*)(fi + (size_t)base * 16);
        for (int idx = tx; idx < 1024; idx += 256) {
            int r  = idx >> 2;
            int c4 = (idx & 3) * 4;
            if (base + r < B) {
                float4 v = fi4[idx];
                float* d = &s_fi[r * 17 + c4];
                d[0] = v.x; d[1] = v.y; d[2] = v.z; d[3] = v.w;
            }
        }
    }
    for (int idx = tx; idx < 128; idx += 256) {
        float w = w_line[idx];
        s_wline2[idx] = pk2(w, w);
    }
    for (int idx = tx; idx < 160; idx += 256) {
        int o2 = idx >> 4, c = idx & 15;
        ulonglong2 w2;
        w2.x = pk2(w_feat[(2 * o2) * 32 + c],     w_feat[(2 * o2) * 32 + 16 + c]);
        w2.y = pk2(w_feat[(2 * o2 + 1) * 32 + c], w_feat[(2 * o2 + 1) * 32 + 16 + c]);
        s_wpk2[idx] = w2;
    }
    if (tx < 16) { float bl = b_line[tx]; s_bline2[tx] = pk2(bl, bl); }
    if (tx < 20) s_bfeat[tx] = b_feat[tx];
    if (tx < 8)  s_sge[tx]   = sigmoidf(emb_phase[tx]);
    if (tx < 4)  { s_wv[tx] = w_veh[tx]; s_bv[tx] = b_veh[tx]; }
    __syncthreads();

    int b = base + tx;
    if (b >= B) return;
    int p  = blockIdx.y;
    int la = d_PLa[p];
    int lb = d_PLb[p];

    const float* f = &s_fi[tx * 17];
    float bit_a = f[la],     bit_b = f[lb];
    float veh_a = f[8 + la], veh_b = f[8 + lb];
    int ia = (int)bit_a, ib = (int)bit_b;

    // packed line features: (laneA, laneB) per dim
    u64 lp[8];
#pragma unroll
    for (int d = 0; d < 4; d++) {
        lp[d]     = pk2(sigmoidf(veh_a * s_wv[d] + s_bv[d]),
                        sigmoidf(veh_b * s_wv[d] + s_bv[d]));
        lp[4 + d] = pk2(s_sge[ia * 4 + d], s_sge[ib * 4 + d]);
    }

    u64 pressd[16];
#pragma unroll
    for (int o = 0; o < 16; o++) {
        u64 acc = s_bline2[o];
#pragma unroll
        for (int d = 0; d < 8; d++)
            acc = f2fma(s_wline2[o * 8 + d], lp[d], acc);
        float xa, xb;
        upk2(xa, xb, acc);
        float pr = fmaxf(xa, 0.0f) + fmaxf(xb, 0.0f);
        pressd[o] = pk2(pr, pr);
    }

    int Bh = B >> 1;
    int bh = b >> 1;
    int sub = b & 1;
    float2* stU = (float2*)g_U4;
    float2* stV = (float2*)g_V4;

#pragma unroll
    for (int o2 = 0; o2 < 10; o2++) {
        u64 accA = pk2(s_bfeat[2 * o2], 0.0f);       // (U incl bias, V)
        u64 accB = pk2(s_bfeat[2 * o2 + 1], 0.0f);
#pragma unroll
        for (int c = 0; c < 16; c++) {
            ulonglong2 w2 = s_wpk2[o2 * 16 + c];
            accA = f2fma(w2.x, pressd[c], accA);
            accB = f2fma(w2.y, pressd[c], accB);
        }
        float uA, vA, uB, vB;
        upk2(uA, vA, accA);
        upk2(uB, vB, accB);
        size_t idx = ((size_t)(p * 10 + o2) * Bh + bh) * 2 + sub;
        stU[idx] = make_float2(uA, uB);
        stV[idx] = make_float2(vA, vB);
    }
}

// ---------------------------------------------------------------------------
// Kernel 2: grid (Bh/256, 56). pair = blockIdx.y (warp-uniform pi/pj),
// thread handles positions t = pair*B + 2*bh, t+1 (coalesced gathers).
// ---------------------------------------------------------------------------
__global__ void __launch_bounds__(256, 2)
frap_k2(const float* __restrict__ emb_const,
        const float* __restrict__ w_const,
        const float* __restrict__ b_const,
        const float* __restrict__ w_comb,
        const float* __restrict__ b_comb,
        const float* __restrict__ w_final,
        const float* __restrict__ b_final,
        const int*   __restrict__ cmask,
        int B)
{
    __shared__ __align__(16) u64 s_ycp[28 * 20];  // (yc[2r][o], yc[2r+1][o])
    __shared__ __align__(16) u64 s_wd[400];       // dup-packed w_comb
    __shared__ u64   s_bcd[20];
    __shared__ float s_wfin[20];
    __shared__ float s_bfin;

    int tx = threadIdx.x;
    for (int idx = tx; idx < 400; idx += 256) {
        float w = w_comb[idx];
        s_wd[idx] = pk2(w, w);
    }
    if (tx < 20) {
        float bc = b_comb[tx];
        s_bcd[tx]  = pk2(bc, bc);
        s_wfin[tx] = w_final[tx];
    }
    if (tx == 0) s_bfin = b_final[0];
    for (int idx = tx; idx < 28 * 20; idx += 256) {
        int r2 = idx / 20;
        int o  = idx - r2 * 20;
        const float* w  = w_const + o * 4;
        const float* e0 = emb_const + cmask[2 * r2] * 4;
        const float* e1 = emb_const + cmask[2 * r2 + 1] * 4;
        float y0 = b_const[o] + w[0]*e0[0] + w[1]*e0[1] + w[2]*e0[2] + w[3]*e0[3];
        float y1 = b_const[o] + w[0]*e1[0] + w[1]*e1[1] + w[2]*e1[2] + w[3]*e1[3];
        s_ycp[idx] = pk2(fmaxf(y0, 0.0f), fmaxf(y1, 0.0f));
    }
    __syncthreads();

    int Bh = B >> 1;
    int bh = blockIdx.x * 256 + tx;
    if (bh >= Bh) return;
    int pair = blockIdx.y;
    int pi = pair / 7;
    int r  = pair - pi * 7;
    int pj = r + (r >= pi ? 1 : 0);

    int t   = pair * B + 2 * bh;     // even
    int rem = t % 56;                // even
    const u64* ycp = s_ycp + (rem >> 1) * 20;

    const float4* Ub = g_U4 + (size_t)pi * 10 * Bh + bh;
    const float4* Vb = g_V4 + (size_t)pj * 10 * Bh + bh;

    u64 Hp[20];
#pragma unroll
    for (int o2 = 0; o2 < 10; o2++) {
        float4 fu = Ub[(size_t)o2 * Bh];
        float4 fv = Vb[(size_t)o2 * Bh];
        float a0 = fmaxf(fu.x + fv.x, 0.0f);   // pos0, o=2o2
        float a1 = fmaxf(fu.z + fv.z, 0.0f);   // pos1, o=2o2
        float b0 = fmaxf(fu.y + fv.y, 0.0f);   // pos0, o=2o2+1
        float b1 = fmaxf(fu.w + fv.w, 0.0f);   // pos1, o=2o2+1
        Hp[2 * o2]     = f2mul(pk2(a0, a1), ycp[2 * o2]);
        Hp[2 * o2 + 1] = f2mul(pk2(b0, b1), ycp[2 * o2 + 1]);
    }

    float s0 = s_bfin, s1 = s_bfin;
#pragma unroll
    for (int o2 = 0; o2 < 20; o2++) {
        const ulonglong2* wr = (const ulonglong2*)(s_wd + o2 * 20);
        u64 a = s_bcd[o2];
#pragma unroll
        for (int k = 0; k < 10; k++) {
            ulonglong2 w2 = wr[k];
            a = f2fma(w2.x, Hp[2 * k],     a);
            a = f2fma(w2.y, Hp[2 * k + 1], a);
        }
        float lo, hi;
        upk2(lo, hi, a);
        float wf = s_wfin[o2];
        s0 += fmaxf(lo, 0.0f) * wf;
        s1 += fmaxf(hi, 0.0f) * wf;
    }

    ((float2*)g_S)[(size_t)pair * Bh + bh] =
        make_float2(fmaxf(s0, 0.0f), fmaxf(s1, 0.0f));
}

// ---------------------------------------------------------------------------
// Kernel 3: block-staged 7-sum. Block handles 256 outputs = 1792 g_S floats
// = 448 float4s, loaded coalesced into smem (two guarded rounds cover
// indices 0..511 >= 448); per-thread stride-7 smem sum.
// ---------------------------------------------------------------------------
__global__ void __launch_bounds__(256, 8)
frap_k3(float* __restrict__ out, int n)
{
    __shared__ __align__(16) float s[1792];
    int tx = threadIdx.x;
    int obase = blockIdx.x * 256;
    size_t sbase = (size_t)obase * 7;

    const float4* g4 = (const float4*)(g_S + sbase);
    int lim = n * 7 - (int)sbase;                 // floats available
#pragma unroll
    for (int k = 0; k < 2; k++) {
        int idx = k * 256 + tx;                   // float4 index; 448 needed
        if (idx < 448 && idx * 4 < lim) {
            float4 v = g4[idx];
            float* d = &s[idx * 4];
            d[0] = v.x; d[1] = v.y; d[2] = v.z; d[3] = v.w;
        }
    }
    __syncthreads();

    int o = obase + tx;
    if (o >= n) return;
    const float* p = &s[tx * 7];
    out[o] = p[0] + p[1] + p[2] + p[3] + p[4] + p[5] + p[6];
}

// ---------------------------------------------------------------------------
extern "C" void kernel_launch(void* const* d_in, const int* in_sizes, int n_in,
                              void* d_out, int out_size)
{
    const float* fi        = (const float*)d_in[0];
    const float* emb_phase = (const float*)d_in[1];
    const float* w_veh     = (const float*)d_in[2];
    const float* b_veh     = (const float*)d_in[3];
    const float* w_line    = (const float*)d_in[4];
    const float* b_line    = (const float*)d_in[5];
    const float* emb_const = (const float*)d_in[6];
    const float* w_feat    = (const float*)d_in[7];
    const float* b_feat    = (const float*)d_in[8];
    const float* w_const   = (const float*)d_in[9];
    const float* b_const   = (const float*)d_in[10];
    const float* w_comb    = (const float*)d_in[11];
    const float* b_comb    = (const float*)d_in[12];
    const float* w_final   = (const float*)d_in[13];
    const float* b_final   = (const float*)d_in[14];
    const int*   cmask     = (const int*)d_in[15];

    int B = in_sizes[0] / 16;
    if (B > BMAX) B = BMAX;
    int Bh = B >> 1;

    dim3 grid1((B + 255) / 256, 8);
    dim3 grid2((Bh + 255) / 256, 56);
    int n = B * 8;
    int blocks3 = (n + 255) / 256;

    frap_k1<<<grid1, 256>>>(fi, emb_phase, w_veh, b_veh, w_line, b_line,
                            w_feat, b_feat, B);
    frap_k2<<<grid2, 256>>>(emb_const, w_const, b_const, w_comb, b_comb,
                            w_final, b_final, cmask, B);
    frap_k3<<<blocks3, 256>>>((float*)d_out, n);
}

// round 14
// speedup vs baseline: 1.0332x; 1.0332x over previous
#include <cuda_runtime.h>
#include <cuda_bf16.h>

#define BMAX 16384

typedef unsigned long long u64;

// Scratch (static device globals — no allocation).
// Pair-interleaved layout: g_U4[p][o2][bh] (p<8, o2<10, bh<B/2), float4 =
//   { U[2bh][p][2o2], U[2bh][p][2o2+1], U[2bh+1][p][2o2], U[2bh+1][p][2o2+1] }
// (b_feat folded into U). Same for V. 10.5 MB each -> L2-resident.
__device__ float4 g_U4[8 * 10 * (BMAX / 2)];
__device__ float4 g_V4[8 * 10 * (BMAX / 2)];
// per-position relu(final) values, summed in groups of 7 by k3
__device__ float g_S[BMAX * 56];

// PHASE_LANES = [[1,3],[5,7],[0,2],[4,6],[0,1],[2,3],[4,5],[6,7]]
__device__ const int d_PLa[8] = {1, 5, 0, 4, 0, 2, 4, 6};
__device__ const int d_PLb[8] = {3, 7, 2, 6, 1, 3, 5, 7};

__device__ __forceinline__ float sigmoidf(float x) {
    return __fdividef(1.0f, 1.0f + __expf(-x));
}
__device__ __forceinline__ u64 pk2(float lo, float hi) {
    u64 r;
    asm("mov.b64 %0, {%1, %2};" : "=l"(r) : "f"(lo), "f"(hi));
    return r;
}
__device__ __forceinline__ void upk2(float& lo, float& hi, u64 v) {
    asm("mov.b64 {%0, %1}, %2;" : "=f"(lo), "=f"(hi) : "l"(v));
}
__device__ __forceinline__ u64 f2fma(u64 a, u64 b, u64 c) {
    u64 d;
    asm("fma.rn.f32x2 %0, %1, %2, %3;" : "=l"(d) : "l"(a), "l"(b), "l"(c));
    return d;
}
__device__ __forceinline__ u64 f2mul(u64 a, u64 b) {
    u64 d;
    asm("mul.rn.f32x2 %0, %1, %2;" : "=l"(d) : "l"(a), "l"(b));
    return d;
}
__device__ __forceinline__ u64 f2add(u64 a, u64 b) {
    u64 d;
    asm("add.rn.f32x2 %0, %1, %2;" : "=l"(d) : "l"(a), "l"(b));
    return d;
}

// ---------------------------------------------------------------------------
// Kernel 1: grid (B/256, 8); p = blockIdx.y, b fast across lanes.
// Split accumulator chains for 2x ILP; 3 blocks/SM.
// ---------------------------------------------------------------------------
__global__ void __launch_bounds__(256, 3)
frap_k1(const float* __restrict__ fi,
        const float* __restrict__ emb_phase,
        const float* __restrict__ w_veh,
        const float* __restrict__ b_veh,
        const float* __restrict__ w_line,
        const float* __restrict__ b_line,
        const float* __restrict__ w_feat,
        const float* __restrict__ b_feat,
        int B)
{
    __shared__ __align__(16) float s_fi[256 * 17];        // padded input tile
    __shared__ __align__(16) u64   s_wline2[128];         // dup-packed (16,8)
    __shared__ __align__(16) ulonglong2 s_wpk2[160];      // [o2][c]: (wA_pk, wB_pk)
    __shared__ u64   s_bline2[16];
    __shared__ float s_bfeat[20];
    __shared__ float s_sge[8];                            // sigmoid(emb_phase)
    __shared__ float s_wv[4], s_bv[4];

    int tx = threadIdx.x;
    int base = blockIdx.x * 256;

    // coalesced staging of the input tile (256 rows x 16 floats)
    {
        const float4* fi4 = (const float4*)(fi + (size_t)base * 16);
        for (int idx = tx; idx < 1024; idx += 256) {
            int r  = idx >> 2;
            int c4 = (idx & 3) * 4;
            if (base + r < B) {
                float4 v = fi4[idx];
                float* d = &s_fi[r * 17 + c4];
                d[0] = v.x; d[1] = v.y; d[2] = v.z; d[3] = v.w;
            }
        }
    }
    for (int idx = tx; idx < 128; idx += 256) {
        float w = w_line[idx];
        s_wline2[idx] = pk2(w, w);
    }
    for (int idx = tx; idx < 160; idx += 256) {
        int o2 = idx >> 4, c = idx & 15;
        ulonglong2 w2;
        w2.x = pk2(w_feat[(2 * o2) * 32 + c],     w_feat[(2 * o2) * 32 + 16 + c]);
        w2.y = pk2(w_feat[(2 * o2 + 1) * 32 + c], w_feat[(2 * o2 + 1) * 32 + 16 + c]);
        s_wpk2[idx] = w2;
    }
    if (tx < 16) { float bl = b_line[tx]; s_bline2[tx] = pk2(bl, bl); }
    if (tx < 20) s_bfeat[tx] = b_feat[tx];
    if (tx < 8)  s_sge[tx]   = sigmoidf(emb_phase[tx]);
    if (tx < 4)  { s_wv[tx] = w_veh[tx]; s_bv[tx] = b_veh[tx]; }
    __syncthreads();

    int b = base + tx;
    if (b >= B) return;
    int p  = blockIdx.y;
    int la = d_PLa[p];
    int lb = d_PLb[p];

    const float* f = &s_fi[tx * 17];
    float bit_a = f[la],     bit_b = f[lb];
    float veh_a = f[8 + la], veh_b = f[8 + lb];
    int ia = (int)bit_a, ib = (int)bit_b;

    // packed line features: (laneA, laneB) per dim
    u64 lp[8];
#pragma unroll
    for (int d = 0; d < 4; d++) {
        lp[d]     = pk2(sigmoidf(veh_a * s_wv[d] + s_bv[d]),
                        sigmoidf(veh_b * s_wv[d] + s_bv[d]));
        lp[4 + d] = pk2(s_sge[ia * 4 + d], s_sge[ib * 4 + d]);
    }

    u64 pressd[16];
#pragma unroll
    for (int o = 0; o < 16; o++) {
        u64 acc0 = s_bline2[o];
        u64 acc1 = pk2(0.0f, 0.0f);
#pragma unroll
        for (int d = 0; d < 4; d++) {
            acc0 = f2fma(s_wline2[o * 8 + d],     lp[d],     acc0);
            acc1 = f2fma(s_wline2[o * 8 + 4 + d], lp[4 + d], acc1);
        }
        u64 acc = f2add(acc0, acc1);
        float xa, xb;
        upk2(xa, xb, acc);
        float pr = fmaxf(xa, 0.0f) + fmaxf(xb, 0.0f);
        pressd[o] = pk2(pr, pr);
    }

    int Bh = B >> 1;
    int bh = b >> 1;
    int sub = b & 1;
    float2* stU = (float2*)g_U4;
    float2* stV = (float2*)g_V4;

#pragma unroll 2
    for (int o2 = 0; o2 < 10; o2++) {
        u64 accA0 = pk2(s_bfeat[2 * o2], 0.0f);       // (U incl bias, V)
        u64 accB0 = pk2(s_bfeat[2 * o2 + 1], 0.0f);
        u64 accA1 = pk2(0.0f, 0.0f);
        u64 accB1 = pk2(0.0f, 0.0f);
#pragma unroll
        for (int c = 0; c < 8; c++) {
            ulonglong2 w2lo = s_wpk2[o2 * 16 + c];
            ulonglong2 w2hi = s_wpk2[o2 * 16 + 8 + c];
            accA0 = f2fma(w2lo.x, pressd[c],     accA0);
            accB0 = f2fma(w2lo.y, pressd[c],     accB0);
            accA1 = f2fma(w2hi.x, pressd[8 + c], accA1);
            accB1 = f2fma(w2hi.y, pressd[8 + c], accB1);
        }
        u64 accA = f2add(accA0, accA1);
        u64 accB = f2add(accB0, accB1);
        float uA, vA, uB, vB;
        upk2(uA, vA, accA);
        upk2(uB, vB, accB);
        size_t idx = ((size_t)(p * 10 + o2) * Bh + bh) * 2 + sub;
        stU[idx] = make_float2(uA, uB);
        stV[idx] = make_float2(vA, vB);
    }
}

// ---------------------------------------------------------------------------
// Kernel 2: grid (Bh/256, 56). pair = blockIdx.y (warp-uniform pi/pj),
// thread handles positions t = pair*B + 2*bh, t+1 (coalesced gathers).
// Comb-row accumulation split into two chains (x/y) for 2x ILP; 3 blocks/SM.
// ---------------------------------------------------------------------------
__global__ void __launch_bounds__(256, 3)
frap_k2(const float* __restrict__ emb_const,
        const float* __restrict__ w_const,
        const float* __restrict__ b_const,
        const float* __restrict__ w_comb,
        const float* __restrict__ b_comb,
        const float* __restrict__ w_final,
        const float* __restrict__ b_final,
        const int*   __restrict__ cmask,
        int B)
{
    __shared__ __align__(16) u64 s_ycp[28 * 20];  // (yc[2r][o], yc[2r+1][o])
    __shared__ __align__(16) u64 s_wd[400];       // dup-packed w_comb
    __shared__ u64   s_bcd[20];
    __shared__ float s_wfin[20];
    __shared__ float s_bfin;

    int tx = threadIdx.x;
    for (int idx = tx; idx < 400; idx += 256) {
        float w = w_comb[idx];
        s_wd[idx] = pk2(w, w);
    }
    if (tx < 20) {
        float bc = b_comb[tx];
        s_bcd[tx]  = pk2(bc, bc);
        s_wfin[tx] = w_final[tx];
    }
    if (tx == 0) s_bfin = b_final[0];
    for (int idx = tx; idx < 28 * 20; idx += 256) {
        int r2 = idx / 20;
        int o  = idx - r2 * 20;
        const float* w  = w_const + o * 4;
        const float* e0 = emb_const + cmask[2 * r2] * 4;
        const float* e1 = emb_const + cmask[2 * r2 + 1] * 4;
        float y0 = b_const[o] + w[0]*e0[0] + w[1]*e0[1] + w[2]*e0[2] + w[3]*e0[3];
        float y1 = b_const[o] + w[0]*e1[0] + w[1]*e1[1] + w[2]*e1[2] + w[3]*e1[3];
        s_ycp[idx] = pk2(fmaxf(y0, 0.0f), fmaxf(y1, 0.0f));
    }
    __syncthreads();

    int Bh = B >> 1;
    int bh = blockIdx.x * 256 + tx;
    if (bh >= Bh) return;
    int pair = blockIdx.y;
    int pi = pair / 7;
    int r  = pair - pi * 7;
    int pj = r + (r >= pi ? 1 : 0);

    int t   = pair * B + 2 * bh;     // even
    int rem = t % 56;                // even
    const u64* ycp = s_ycp + (rem >> 1) * 20;

    const float4* Ub = g_U4 + (size_t)pi * 10 * Bh + bh;
    const float4* Vb = g_V4 + (size_t)pj * 10 * Bh + bh;

    u64 Hp[20];
#pragma unroll
    for (int o2 = 0; o2 < 10; o2++) {
        float4 fu = Ub[(size_t)o2 * Bh];
        float4 fv = Vb[(size_t)o2 * Bh];
        float a0 = fmaxf(fu.x + fv.x, 0.0f);   // pos0, o=2o2
        float a1 = fmaxf(fu.z + fv.z, 0.0f);   // pos1, o=2o2
        float b0 = fmaxf(fu.y + fv.y, 0.0f);   // pos0, o=2o2+1
        float b1 = fmaxf(fu.w + fv.w, 0.0f);   // pos1, o=2o2+1
        Hp[2 * o2]     = f2mul(pk2(a0, a1), ycp[2 * o2]);
        Hp[2 * o2 + 1] = f2mul(pk2(b0, b1), ycp[2 * o2 + 1]);
    }

    float s0 = s_bfin, s1 = s_bfin;
#pragma unroll 5
    for (int o2 = 0; o2 < 20; o2++) {
        const ulonglong2* wr = (const ulonglong2*)(s_wd + o2 * 20);
        u64 ax = s_bcd[o2];
        u64 ay = pk2(0.0f, 0.0f);
#pragma unroll
        for (int k = 0; k < 10; k++) {
            ulonglong2 w2 = wr[k];
            ax = f2fma(w2.x, Hp[2 * k],     ax);
            ay = f2fma(w2.y, Hp[2 * k + 1], ay);
        }
        u64 a = f2add(ax, ay);
        float lo, hi;
        upk2(lo, hi, a);
        float wf = s_wfin[o2];
        s0 += fmaxf(lo, 0.0f) * wf;
        s1 += fmaxf(hi, 0.0f) * wf;
    }

    ((float2*)g_S)[(size_t)pair * Bh + bh] =
        make_float2(fmaxf(s0, 0.0f), fmaxf(s1, 0.0f));
}

// ---------------------------------------------------------------------------
// Kernel 3: block-staged 7-sum. Block handles 256 outputs = 1792 g_S floats
// = 448 float4s, loaded coalesced into smem; per-thread stride-7 smem sum.
// ---------------------------------------------------------------------------
__global__ void __launch_bounds__(256, 8)
frap_k3(float* __restrict__ out, int n)
{
    __shared__ __align__(16) float s[1792];
    int tx = threadIdx.x;
    int obase = blockIdx.x * 256;
    size_t sbase = (size_t)obase * 7;

    const float4* g4 = (const float4*)(g_S + sbase);
    int lim = n * 7 - (int)sbase;                 // floats available
#pragma unroll
    for (int k = 0; k < 2; k++) {
        int idx = k * 256 + tx;                   // float4 index; 448 needed
        if (idx < 448 && idx * 4 < lim) {
            float4 v = g4[idx];
            float* d = &s[idx * 4];
            d[0] = v.x; d[1] = v.y; d[2] = v.z; d[3] = v.w;
        }
    }
    __syncthreads();

    int o = obase + tx;
    if (o >= n) return;
    const float* p = &s[tx * 7];
    out[o] = p[0] + p[1] + p[2] + p[3] + p[4] + p[5] + p[6];
}

// ---------------------------------------------------------------------------
extern "C" void kernel_launch(void* const* d_in, const int* in_sizes, int n_in,
                              void* d_out, int out_size)
{
    const float* fi        = (const float*)d_in[0];
    const float* emb_phase = (const float*)d_in[1];
    const float* w_veh     = (const float*)d_in[2];
    const float* b_veh     = (const float*)d_in[3];
    const float* w_line    = (const float*)d_in[4];
    const float* b_line    = (const float*)d_in[5];
    const float* emb_const = (const float*)d_in[6];
    const float* w_feat    = (const float*)d_in[7];
    const float* b_feat    = (const float*)d_in[8];
    const float* w_const   = (const float*)d_in[9];
    const float* b_const   = (const float*)d_in[10];
    const float* w_comb    = (const float*)d_in[11];
    const float* b_comb    = (const float*)d_in[12];
    const float* w_final   = (const float*)d_in[13];
    const float* b_final   = (const float*)d_in[14];
    const int*   cmask     = (const int*)d_in[15];

    int B = in_sizes[0] / 16;
    if (B > BMAX) B = BMAX;
    int Bh = B >> 1;

    dim3 grid1((B + 255) / 256, 8);
    dim3 grid2((Bh + 255) / 256, 56);
    int n = B * 8;
    int blocks3 = (n + 255) / 256;

    frap_k1<<<grid1, 256>>>(fi, emb_phase, w_veh, b_veh, w_line, b_line,
                            w_feat, b_feat, B);
    frap_k2<<<grid2, 256>>>(emb_const, w_const, b_const, w_comb, b_comb,
                            w_final, b_final, cmask, B);
    frap_k3<<<blocks3, 256>>>((float*)d_out, n);
}

// round 15
// speedup vs baseline: 1.1666x; 1.1291x over previous
#include <cuda_runtime.h>
#include <cuda_bf16.h>

#define BMAX 16384

typedef unsigned long long u64;

// Scratch (static device globals — no allocation).
// float2 view: g_U2[(p*10+o2)*B + b] = (U[b][p][2*o2], U[b][p][2*o2+1]),
// b_feat folded into U. Same for V. 10.5 MB each -> L2-resident.
__device__ float4 g_U4[8 * 10 * (BMAX / 2)];
__device__ float4 g_V4[8 * 10 * (BMAX / 2)];
// per-position relu(final) values, summed in groups of 7 by k3
__device__ float g_S[BMAX * 56];

// PHASE_LANES = [[1,3],[5,7],[0,2],[4,6],[0,1],[2,3],[4,5],[6,7]]
__device__ const int d_PLa[8] = {1, 5, 0, 4, 0, 2, 4, 6};
__device__ const int d_PLb[8] = {3, 7, 2, 6, 1, 3, 5, 7};

__device__ __forceinline__ float sigmoidf(float x) {
    return __fdividef(1.0f, 1.0f + __expf(-x));
}
__device__ __forceinline__ u64 pk2(float lo, float hi) {
    u64 r;
    asm("mov.b64 %0, {%1, %2};" : "=l"(r) : "f"(lo), "f"(hi));
    return r;
}
__device__ __forceinline__ void upk2(float& lo, float& hi, u64 v) {
    asm("mov.b64 {%0, %1}, %2;" : "=f"(lo), "=f"(hi) : "l"(v));
}
__device__ __forceinline__ u64 f2fma(u64 a, u64 b, u64 c) {
    u64 d;
    asm("fma.rn.f32x2 %0, %1, %2, %3;" : "=l"(d) : "l"(a), "l"(b), "l"(c));
    return d;
}
__device__ __forceinline__ u64 f2mul(u64 a, u64 b) {
    u64 d;
    asm("mul.rn.f32x2 %0, %1, %2;" : "=l"(d) : "l"(a), "l"(b));
    return d;
}
__device__ __forceinline__ u64 f2add(u64 a, u64 b) {
    u64 d;
    asm("add.rn.f32x2 %0, %1, %2;" : "=l"(d) : "l"(a), "l"(b));
    return d;
}

// ---------------------------------------------------------------------------
// Kernel 1: grid (B/256, 8); p = blockIdx.y, b fast across lanes.
// press held as natural feature-pairs (8 u64); projection weights as
// (U-pair, V-pair) ulonglong2 rows -> horizontal add per output.
// Register diet targets 4 blocks/SM.
// ---------------------------------------------------------------------------
__global__ void __launch_bounds__(256, 4)
frap_k1(const float* __restrict__ fi,
        const float* __restrict__ emb_phase,
        const float* __restrict__ w_veh,
        const float* __restrict__ b_veh,
        const float* __restrict__ w_line,
        const float* __restrict__ b_line,
        const float* __restrict__ w_feat,
        const float* __restrict__ b_feat,
        int B)
{
    __shared__ __align__(16) float s_fi[256 * 17];        // padded input tile
    __shared__ __align__(16) u64   s_wline2[128];         // dup-packed (16,8)
    __shared__ __align__(16) ulonglong2 s_wproj[160];     // [o][c8]: (U-pair, V-pair)
    __shared__ u64   s_bline2[16];
    __shared__ float s_bfeat[20];
    __shared__ float s_sge[8];                            // sigmoid(emb_phase)
    __shared__ float s_wv[4], s_bv[4];

    int tx = threadIdx.x;
    int base = blockIdx.x * 256;

    // coalesced staging of the input tile (256 rows x 16 floats)
    {
        const float4* fi4 = (const float4*)(fi + (size_t)base * 16);
        for (int idx = tx; idx < 1024; idx += 256) {
            int r  = idx >> 2;
            int c4 = (idx & 3) * 4;
            if (base + r < B) {
                float4 v = fi4[idx];
                float* d = &s_fi[r * 17 + c4];
                d[0] = v.x; d[1] = v.y; d[2] = v.z; d[3] = v.w;
            }
        }
    }
    for (int idx = tx; idx < 128; idx += 256) {
        float w = w_line[idx];
        s_wline2[idx] = pk2(w, w);
    }
    for (int idx = tx; idx < 160; idx += 256) {
        int o = idx >> 3, c = idx & 7;                    // o<20, c = feature pair
        ulonglong2 w2;
        w2.x = pk2(w_feat[o * 32 + 2 * c],      w_feat[o * 32 + 2 * c + 1]);
        w2.y = pk2(w_feat[o * 32 + 16 + 2 * c], w_feat[o * 32 + 17 + 2 * c]);
        s_wproj[idx] = w2;
    }
    if (tx < 16) { float bl = b_line[tx]; s_bline2[tx] = pk2(bl, bl); }
    if (tx < 20) s_bfeat[tx] = b_feat[tx];
    if (tx < 8)  s_sge[tx]   = sigmoidf(emb_phase[tx]);
    if (tx < 4)  { s_wv[tx] = w_veh[tx]; s_bv[tx] = b_veh[tx]; }
    __syncthreads();

    int b = base + tx;
    if (b >= B) return;
    int p  = blockIdx.y;
    int la = d_PLa[p];
    int lb = d_PLb[p];

    const float* f = &s_fi[tx * 17];
    float bit_a = f[la],     bit_b = f[lb];
    float veh_a = f[8 + la], veh_b = f[8 + lb];
    int ia = (int)bit_a, ib = (int)bit_b;

    // packed line features: (laneA, laneB) per dim
    u64 lp[8];
#pragma unroll
    for (int d = 0; d < 4; d++) {
        lp[d]     = pk2(sigmoidf(veh_a * s_wv[d] + s_bv[d]),
                        sigmoidf(veh_b * s_wv[d] + s_bv[d]));
        lp[4 + d] = pk2(s_sge[ia * 4 + d], s_sge[ib * 4 + d]);
    }

    // press as natural pairs: pp[c] = (press[2c], press[2c+1])
    u64 pp[8];
    float pr_even = 0.0f;
#pragma unroll
    for (int o = 0; o < 16; o++) {
        u64 acc0 = s_bline2[o];
        u64 acc1 = pk2(0.0f, 0.0f);
#pragma unroll
        for (int d = 0; d < 4; d++) {
            acc0 = f2fma(s_wline2[o * 8 + d],     lp[d],     acc0);
            acc1 = f2fma(s_wline2[o * 8 + 4 + d], lp[4 + d], acc1);
        }
        u64 acc = f2add(acc0, acc1);
        float xa, xb;
        upk2(xa, xb, acc);
        float pr = fmaxf(xa, 0.0f) + fmaxf(xb, 0.0f);
        if (o & 1) pp[o >> 1] = pk2(pr_even, pr);
        else       pr_even = pr;
    }

    int Bh = B >> 1;
    float2* stU = (float2*)g_U4;
    float2* stV = (float2*)g_V4;
    size_t sidx = ((size_t)p * 10 * Bh) * 2 + b;   // float2 index [p*10+o2][b]

#pragma unroll 2
    for (int o2 = 0; o2 < 10; o2++) {
        float uo[2], vo[2];
#pragma unroll
        for (int s = 0; s < 2; s++) {
            int o = 2 * o2 + s;
            u64 accU = pk2(s_bfeat[o], 0.0f);      // bias in lo half
            u64 accV = pk2(0.0f, 0.0f);
#pragma unroll
            for (int c = 0; c < 8; c++) {
                ulonglong2 w2 = s_wproj[o * 8 + c];
                accU = f2fma(w2.x, pp[c], accU);
                accV = f2fma(w2.y, pp[c], accV);
            }
            float ul, uh, vl, vh;
            upk2(ul, uh, accU);
            upk2(vl, vh, accV);
            uo[s] = ul + uh;
            vo[s] = vl + vh;
        }
        stU[sidx + (size_t)o2 * B] = make_float2(uo[0], uo[1]);
        stV[sidx + (size_t)o2 * B] = make_float2(vo[0], vo[1]);
    }
}

// ---------------------------------------------------------------------------
// Kernel 2: grid (Bh/256, 56). pair = blockIdx.y (warp-uniform pi/pj),
// thread handles positions t = pair*B + 2*bh, t+1 (coalesced gathers).
// Hp packs feature pairs per position; weights NON-duplicated (10 u64/row):
// half the weight-LDS of the dup-packed scheme, same FMA, 2 chains.
// ---------------------------------------------------------------------------
__global__ void __launch_bounds__(256, 3)
frap_k2(const float* __restrict__ emb_const,
        const float* __restrict__ w_const,
        const float* __restrict__ b_const,
        const float* __restrict__ w_comb,
        const float* __restrict__ b_comb,
        const float* __restrict__ w_final,
        const float* __restrict__ b_final,
        const int*   __restrict__ cmask,
        int B)
{
    __shared__ __align__(16) u64 s_ycp[56 * 10];  // [r][o2] = (yc[r][2o2], yc[r][2o2+1])
    __shared__ __align__(16) u64 s_w10[200];      // [o2][k] = (w[o2][2k], w[o2][2k+1])
    __shared__ float s_bc[20];
    __shared__ float s_wfin[20];
    __shared__ float s_bfin;

    int tx = threadIdx.x;
    for (int idx = tx; idx < 200; idx += 256) {
        int o2 = idx / 10, k = idx - o2 * 10;
        s_w10[idx] = pk2(w_comb[o2 * 20 + 2 * k], w_comb[o2 * 20 + 2 * k + 1]);
    }
    if (tx < 20) {
        s_bc[tx]   = b_comb[tx];
        s_wfin[tx] = w_final[tx];
    }
    if (tx == 0) s_bfin = b_final[0];
    for (int idx = tx; idx < 56 * 10; idx += 256) {
        int r  = idx / 10;
        int oc = idx - r * 10;
        const float* e  = emb_const + cmask[r] * 4;
        const float* w0 = w_const + (2 * oc) * 4;
        const float* w1 = w_const + (2 * oc + 1) * 4;
        float y0 = b_const[2 * oc]     + w0[0]*e[0] + w0[1]*e[1] + w0[2]*e[2] + w0[3]*e[3];
        float y1 = b_const[2 * oc + 1] + w1[0]*e[0] + w1[1]*e[1] + w1[2]*e[2] + w1[3]*e[3];
        s_ycp[idx] = pk2(fmaxf(y0, 0.0f), fmaxf(y1, 0.0f));
    }
    __syncthreads();

    int Bh = B >> 1;
    int bh = blockIdx.x * 256 + tx;
    if (bh >= Bh) return;
    int pair = blockIdx.y;
    int pi = pair / 7;
    int r  = pair - pi * 7;
    int pj = r + (r >= pi ? 1 : 0);

    int t   = pair * B + 2 * bh;     // even
    int rem = t % 56;                // even
    const u64* ycp0 = s_ycp + rem * 10;        // pos0 row
    const u64* ycp1 = ycp0 + 10;               // pos1 row (rem+1 < 56)

    const float4* Ub = g_U4 + (size_t)pi * 10 * Bh + bh;
    const float4* Vb = g_V4 + (size_t)pj * 10 * Bh + bh;

    u64 Hp0[10], Hp1[10];                      // feature-pair packed per position
#pragma unroll
    for (int o2 = 0; o2 < 10; o2++) {
        float4 fu = Ub[(size_t)o2 * Bh];
        float4 fv = Vb[(size_t)o2 * Bh];
        Hp0[o2] = f2mul(pk2(fmaxf(fu.x + fv.x, 0.0f),
                            fmaxf(fu.y + fv.y, 0.0f)), ycp0[o2]);
        Hp1[o2] = f2mul(pk2(fmaxf(fu.z + fv.z, 0.0f),
                            fmaxf(fu.w + fv.w, 0.0f)), ycp1[o2]);
    }

    float s0 = s_bfin, s1 = s_bfin;
#pragma unroll 4
    for (int o2 = 0; o2 < 20; o2++) {
        const ulonglong2* wr = (const ulonglong2*)(s_w10 + o2 * 10);
        float bc = s_bc[o2];
        u64 a0 = pk2(bc, 0.0f);
        u64 a1 = pk2(bc, 0.0f);
#pragma unroll
        for (int k = 0; k < 5; k++) {
            ulonglong2 w2 = wr[k];
            a0 = f2fma(w2.x, Hp0[2 * k],     a0);
            a0 = f2fma(w2.y, Hp0[2 * k + 1], a0);
            a1 = f2fma(w2.x, Hp1[2 * k],     a1);
            a1 = f2fma(w2.y, Hp1[2 * k + 1], a1);
        }
        float l0, h0, l1, h1;
        upk2(l0, h0, a0);
        upk2(l1, h1, a1);
        float wf = s_wfin[o2];
        s0 += fmaxf(l0 + h0, 0.0f) * wf;
        s1 += fmaxf(l1 + h1, 0.0f) * wf;
    }

    ((float2*)g_S)[(size_t)pair * Bh + bh] =
        make_float2(fmaxf(s0, 0.0f), fmaxf(s1, 0.0f));
}

// ---------------------------------------------------------------------------
// Kernel 3: block-staged 7-sum. Block handles 256 outputs = 1792 g_S floats
// = 448 float4s, loaded coalesced into smem; per-thread stride-7 smem sum.
// ---------------------------------------------------------------------------
__global__ void __launch_bounds__(256, 8)
frap_k3(float* __restrict__ out, int n)
{
    __shared__ __align__(16) float s[1792];
    int tx = threadIdx.x;
    int obase = blockIdx.x * 256;
    size_t sbase = (size_t)obase * 7;

    const float4* g4 = (const float4*)(g_S + sbase);
    int lim = n * 7 - (int)sbase;                 // floats available
#pragma unroll
    for (int k = 0; k < 2; k++) {
        int idx = k * 256 + tx;                   // float4 index; 448 needed
        if (idx < 448 && idx * 4 < lim) {
            float4 v = g4[idx];
            float* d = &s[idx * 4];
            d[0] = v.x; d[1] = v.y; d[2] = v.z; d[3] = v.w;
        }
    }
    __syncthreads();

    int o = obase + tx;
    if (o >= n) return;
    const float* p = &s[tx * 7];
    out[o] = p[0] + p[1] + p[2] + p[3] + p[4] + p[5] + p[6];
}

// ---------------------------------------------------------------------------
extern "C" void kernel_launch(void* const* d_in, const int* in_sizes, int n_in,
                              void* d_out, int out_size)
{
    const float* fi        = (const float*)d_in[0];
    const float* emb_phase = (const float*)d_in[1];
    const float* w_veh     = (const float*)d_in[2];
    const float* b_veh     = (const float*)d_in[3];
    const float* w_line    = (const float*)d_in[4];
    const float* b_line    = (const float*)d_in[5];
    const float* emb_const = (const float*)d_in[6];
    const float* w_feat    = (const float*)d_in[7];
    const float* b_feat    = (const float*)d_in[8];
    const float* w_const   = (const float*)d_in[9];
    const float* b_const   = (const float*)d_in[10];
    const float* w_comb    = (const float*)d_in[11];
    const float* b_comb    = (const float*)d_in[12];
    const float* w_final   = (const float*)d_in[13];
    const float* b_final   = (const float*)d_in[14];
    const int*   cmask     = (const int*)d_in[15];

    int B = in_sizes[0] / 16;
    if (B > BMAX) B = BMAX;
    int Bh = B >> 1;

    dim3 grid1((B + 255) / 256, 8);
    dim3 grid2((Bh + 255) / 256, 56);
    int n = B * 8;
    int blocks3 = (n + 255) / 256;

    frap_k1<<<grid1, 256>>>(fi, emb_phase, w_veh, b_veh, w_line, b_line,
                            w_feat, b_feat, B);
    frap_k2<<<grid2, 256>>>(emb_const, w_const, b_const, w_comb, b_comb,
                            w_final, b_final, cmask, B);
    frap_k3<<<blocks3, 256>>>((float*)d_out, n);
}